// round 2
// baseline (speedup 1.0000x reference)
#include <cuda_runtime.h>
#include <cuda_bf16.h>
#include <math.h>

#define NN   100000
#define EE   1600000
#define TOT  (EE + NN)
#define HIDD 128
#define EPSV 1e-5f

// ---------------- static scratch (no allocations allowed) ----------------
__device__ float g_deg[NN];
__device__ float g_dinv[NN];
__device__ int   g_srcx[TOT];
__device__ int   g_dstx[TOT];
__device__ float g_norm[TOT];
__device__ float g_t[(size_t)NN * HIDD];     // GEMM output (pre-aggregation)
__device__ float g_agg[(size_t)NN * HIDD];   // aggregation accumulator
__device__ float g_h[(size_t)NN * HIDD];     // layer activation
__device__ float g_stats[2 * HIDD];          // per-column sum / sumsq
__device__ float g_Wcat[HIDD * HIDD];        // [Wmu | Wls]

// ---------------- graph preprocessing ----------------
__global__ void k_init_deg() {
    int i = blockIdx.x * blockDim.x + threadIdx.x;
    if (i < NN) g_deg[i] = 1.0f;  // self-loop
}

__global__ void k_deg_accum(const int* __restrict__ dst) {
    int i = blockIdx.x * blockDim.x + threadIdx.x;
    if (i < EE) atomicAdd(&g_deg[dst[i]], 1.0f);
}

__global__ void k_dinv() {
    int i = blockIdx.x * blockDim.x + threadIdx.x;
    if (i < NN) g_dinv[i] = rsqrtf(g_deg[i]);
}

__global__ void k_build_edges(const int* __restrict__ src, const int* __restrict__ dst) {
    for (int e = blockIdx.x * blockDim.x + threadIdx.x; e < TOT;
         e += gridDim.x * blockDim.x) {
        if (e < EE) {
            int s = src[e], d = dst[e];
            g_srcx[e] = s; g_dstx[e] = d;
            g_norm[e] = g_dinv[s] * g_dinv[d];
        } else {
            int i = e - EE;
            g_srcx[e] = i; g_dstx[e] = i;
            float di = g_dinv[i];
            g_norm[e] = di * di;
        }
    }
}

// ---------------- zero agg + stats in one kernel ----------------
__global__ void k_zero_agg() {
    size_t tot = (size_t)NN * HIDD / 4;
    float4* p = (float4*)g_agg;
    size_t i0 = (size_t)blockIdx.x * blockDim.x + threadIdx.x;
    for (size_t i = i0; i < tot; i += (size_t)gridDim.x * blockDim.x)
        p[i] = make_float4(0.f, 0.f, 0.f, 0.f);
    if (i0 < 2 * HIDD) g_stats[i0] = 0.0f;
}

// ---------------- SGEMM: g_t[n,128] = A[n,K] @ B[K,128] ----------------
// SRC: 0 = A comes from Aext (x, K=256); 1 = A is g_h, B is Bext (W2);
//      2 = A is g_h, B is g_Wcat.
template <int SRC>
__global__ void __launch_bounds__(256) k_sgemm(const float* __restrict__ Aext,
                                               const float* __restrict__ Bext) {
    const int K = (SRC == 0) ? 256 : 128;
    const float* A = (SRC == 0) ? Aext : g_h;
    const float* B = (SRC == 2) ? g_Wcat : Bext;
    float* C = g_t;

    __shared__ float As[16][132];  // padded, transposed: As[k][row]
    __shared__ float Bs[16][128];
    int row0 = blockIdx.x * 128;
    int tid = threadIdx.x;
    int tx = tid & 15;   // col-tile of 8
    int ty = tid >> 4;   // row-tile of 8

    float acc[8][8];
#pragma unroll
    for (int i = 0; i < 8; i++)
#pragma unroll
        for (int j = 0; j < 8; j++) acc[i][j] = 0.0f;

    for (int k0 = 0; k0 < K; k0 += 16) {
#pragma unroll
        for (int l = 0; l < 2; l++) {
            int f  = tid + l * 256;   // 0..511 float4 slots of A tile (128x16)
            int r  = f >> 2;
            int c4 = f & 3;
            int gr = row0 + r;
            float4 v = make_float4(0.f, 0.f, 0.f, 0.f);
            if (gr < NN) v = *(const float4*)(A + (size_t)gr * K + k0 + c4 * 4);
            As[c4 * 4 + 0][r] = v.x;
            As[c4 * 4 + 1][r] = v.y;
            As[c4 * 4 + 2][r] = v.z;
            As[c4 * 4 + 3][r] = v.w;
        }
#pragma unroll
        for (int l = 0; l < 2; l++) {
            int f  = tid + l * 256;   // 0..511 float4 slots of B tile (16x128)
            int kr = f >> 5;
            int c4 = f & 31;
            *(float4*)&Bs[kr][c4 * 4] =
                *(const float4*)(B + (size_t)(k0 + kr) * 128 + c4 * 4);
        }
        __syncthreads();
#pragma unroll
        for (int k = 0; k < 16; k++) {
            float4 a0 = *(float4*)&As[k][ty * 8];
            float4 a1 = *(float4*)&As[k][ty * 8 + 4];
            float4 b0 = *(float4*)&Bs[k][tx * 8];
            float4 b1 = *(float4*)&Bs[k][tx * 8 + 4];
            float a[8] = {a0.x, a0.y, a0.z, a0.w, a1.x, a1.y, a1.z, a1.w};
            float b[8] = {b0.x, b0.y, b0.z, b0.w, b1.x, b1.y, b1.z, b1.w};
#pragma unroll
            for (int i = 0; i < 8; i++)
#pragma unroll
                for (int j = 0; j < 8; j++) acc[i][j] += a[i] * b[j];
        }
        __syncthreads();
    }
#pragma unroll
    for (int i = 0; i < 8; i++) {
        int gr = row0 + ty * 8 + i;
        if (gr < NN) {
            *(float4*)(C + (size_t)gr * 128 + tx * 8) =
                make_float4(acc[i][0], acc[i][1], acc[i][2], acc[i][3]);
            *(float4*)(C + (size_t)gr * 128 + tx * 8 + 4) =
                make_float4(acc[i][4], acc[i][5], acc[i][6], acc[i][7]);
        }
    }
}

// ---------------- edge scatter: g_agg[dst] += g_t[src] * norm ----------------
__global__ void __launch_bounds__(256) k_scatter() {
    int gw   = (blockIdx.x * blockDim.x + threadIdx.x) >> 5;
    int lane = threadIdx.x & 31;
    int nw   = (gridDim.x * blockDim.x) >> 5;
    for (int e = gw; e < TOT; e += nw) {
        int   s = g_srcx[e];
        int   d = g_dstx[e];
        float w = g_norm[e];
        float4 v = *(const float4*)(g_t + (size_t)s * 128 + lane * 4);
        float* out = g_agg + (size_t)d * 128 + lane * 4;
        asm volatile("red.global.add.v4.f32 [%0], {%1,%2,%3,%4};"
                     :: "l"(out), "f"(v.x * w), "f"(v.y * w),
                        "f"(v.z * w), "f"(v.w * w)
                     : "memory");
    }
}

// ---------------- BatchNorm stats over (g_agg + b) ----------------
__global__ void k_bn_stats(const float* __restrict__ b) {
    int c = threadIdx.x;  // 128 threads
    float bias = b[c];
    float s = 0.f, ss = 0.f;
    for (int r = blockIdx.x; r < NN; r += gridDim.x) {
        float v = g_agg[(size_t)r * 128 + c] + bias;
        s += v;
        ss += v * v;
    }
    atomicAdd(&g_stats[c], s);
    atomicAdd(&g_stats[128 + c], ss);
}

__global__ void k_bn_apply_relu(const float* __restrict__ b,
                                const float* __restrict__ g,
                                const float* __restrict__ bt) {
    size_t tot = (size_t)NN * 128;
    for (size_t i = (size_t)blockIdx.x * blockDim.x + threadIdx.x; i < tot;
         i += (size_t)gridDim.x * blockDim.x) {
        int c = (int)(i & 127);
        float m   = g_stats[c] * (1.0f / NN);
        float var = g_stats[128 + c] * (1.0f / NN) - m * m;
        float v = (g_agg[i] + b[c] - m) * rsqrtf(var + EPSV) * g[c] + bt[c];
        g_h[i] = fmaxf(v, 0.0f);
    }
}

// ---------------- pack [Wmu | Wls] ----------------
__global__ void k_pack_w(const float* __restrict__ Wmu, const float* __restrict__ Wls) {
    int i = blockIdx.x * blockDim.x + threadIdx.x;
    if (i < 128 * 128) {
        int k = i >> 7, j = i & 127;
        g_Wcat[i] = (j < 64) ? Wmu[k * 64 + j] : Wls[k * 64 + (j - 64)];
    }
}

// ---------------- final output: split + bias ----------------
__global__ void k_out(const float* __restrict__ bmu, const float* __restrict__ bls,
                      float* __restrict__ out) {
    size_t tot = (size_t)NN * 64;
    for (size_t i = (size_t)blockIdx.x * blockDim.x + threadIdx.x; i < tot;
         i += (size_t)gridDim.x * blockDim.x) {
        size_t r = i >> 6;
        int    j = (int)(i & 63);
        out[i]       = g_agg[r * 128 + j]      + bmu[j];
        out[tot + i] = g_agg[r * 128 + 64 + j] + bls[j];
    }
}

// ---------------- launch: kernel launches ONLY ----------------
extern "C" void kernel_launch(void* const* d_in, const int* in_sizes, int n_in,
                              void* d_out, int out_size) {
    const float* x   = (const float*)d_in[0];
    const float* W1  = (const float*)d_in[1];
    const float* b1  = (const float*)d_in[2];
    const float* g1  = (const float*)d_in[3];
    const float* bt1 = (const float*)d_in[4];
    const float* W2  = (const float*)d_in[5];
    const float* b2  = (const float*)d_in[6];
    const float* g2  = (const float*)d_in[7];
    const float* bt2 = (const float*)d_in[8];
    const float* Wmu = (const float*)d_in[9];
    const float* bmu = (const float*)d_in[10];
    const float* Wls = (const float*)d_in[11];
    const float* bls = (const float*)d_in[12];
    const int*   ei  = (const int*)d_in[13];
    const int* src = ei;
    const int* dst = ei + EE;
    float* out = (float*)d_out;

    const int GEMM_GRID = (NN + 127) / 128;

    // --- graph normalization ---
    k_init_deg<<<(NN + 255) / 256, 256>>>();
    k_deg_accum<<<(EE + 255) / 256, 256>>>(dst);
    k_dinv<<<(NN + 255) / 256, 256>>>();
    k_build_edges<<<4096, 256>>>(src, dst);

    // --- layer 1: conv(x,W1) -> BN -> ReLU ---
    k_sgemm<0><<<GEMM_GRID, 256>>>(x, W1);
    k_zero_agg<<<2048, 256>>>();
    k_scatter<<<4096, 256>>>();
    k_bn_stats<<<512, 128>>>(b1);
    k_bn_apply_relu<<<2048, 256>>>(b1, g1, bt1);

    // --- layer 2: conv(h,W2) -> BN -> ReLU ---
    k_sgemm<1><<<GEMM_GRID, 256>>>(nullptr, W2);
    k_zero_agg<<<2048, 256>>>();
    k_scatter<<<4096, 256>>>();
    k_bn_stats<<<512, 128>>>(b2);
    k_bn_apply_relu<<<2048, 256>>>(b2, g2, bt2);

    // --- layer 3: fused mu/logstd conv ---
    k_pack_w<<<64, 256>>>(Wmu, Wls);
    k_sgemm<2><<<GEMM_GRID, 256>>>(nullptr, nullptr);
    k_zero_agg<<<2048, 256>>>();
    k_scatter<<<4096, 256>>>();
    k_out<<<2048, 256>>>(bmu, bls, out);
}

// round 3
// speedup vs baseline: 1.6764x; 1.6764x over previous
#include <cuda_runtime.h>
#include <cuda_bf16.h>
#include <math.h>

#define NN   100000
#define EE   1600000
#define TOT  (EE + NN)
#define HIDD 128
#define EPSV 1e-5f
#define NB   98        // ceil(NN / 1024)

// ---------------- static scratch (no allocations allowed) ----------------
__device__ int   g_cnt[NN];                  // per-dst message count (incl self-loop)
__device__ int   g_rowptr[NN + 1];
__device__ int   g_fill[NN];
__device__ float g_dinv[NN];
__device__ int   g_bsum[NB];
__device__ int   g_boff[NB];
__device__ __align__(16) int2  g_csr[TOT];   // {src, norm-as-bits} sorted by dst
__device__ __align__(16) float g_t[(size_t)NN * HIDD];    // GEMM output
__device__ __align__(16) float g_agg[(size_t)NN * HIDD];  // aggregated (+bias)
__device__ float g_stats[2 * HIDD];          // column sum / sumsq
__device__ float g_scale[HIDD];              // BN: rstd*gamma
__device__ float g_shift[HIDD];              // BN: beta - mean*rstd*gamma
__device__ float g_Wcat[HIDD * HIDD];        // [Wmu | Wls]

// ---------------- graph preprocessing ----------------
__global__ void k_init() {
    int i = blockIdx.x * blockDim.x + threadIdx.x;
    if (i < NN) g_cnt[i] = 1;  // self-loop
}

__global__ void k_count(const int* __restrict__ dst) {
    int i = blockIdx.x * blockDim.x + threadIdx.x;
    if (i < EE) atomicAdd(&g_cnt[dst[i]], 1);
}

__global__ void k_dinv() {
    int i = blockIdx.x * blockDim.x + threadIdx.x;
    if (i < NN) {
        g_dinv[i] = rsqrtf((float)g_cnt[i]);
        g_fill[i] = 0;
    }
}

// block-wise inclusive scan of g_cnt -> g_rowptr[i+1], block totals -> g_bsum
__global__ void k_scan1() {
    __shared__ int sh[1024];
    int t = threadIdx.x;
    int i = blockIdx.x * 1024 + t;
    int v = (i < NN) ? g_cnt[i] : 0;
    sh[t] = v;
    __syncthreads();
    for (int off = 1; off < 1024; off <<= 1) {
        int add = (t >= off) ? sh[t - off] : 0;
        __syncthreads();
        sh[t] += add;
        __syncthreads();
    }
    if (i < NN) g_rowptr[i + 1] = sh[t];
    if (t == 1023) g_bsum[blockIdx.x] = sh[t];
}

__global__ void k_scan2() {  // exclusive scan of 98 block sums (1 thread)
    int s = 0;
    for (int b = 0; b < NB; b++) { g_boff[b] = s; s += g_bsum[b]; }
}

__global__ void k_scan3() {
    int t = threadIdx.x;
    int i = blockIdx.x * 1024 + t;
    if (i < NN) g_rowptr[i + 1] += g_boff[blockIdx.x];
    if (i == 0) g_rowptr[0] = 0;
}

__global__ void k_fill(const int* __restrict__ src, const int* __restrict__ dst) {
    for (int e = blockIdx.x * blockDim.x + threadIdx.x; e < TOT;
         e += gridDim.x * blockDim.x) {
        int s, d; float w;
        if (e < EE) {
            s = src[e]; d = dst[e];
            w = g_dinv[s] * g_dinv[d];
        } else {
            s = d = e - EE;
            float di = g_dinv[s];
            w = di * di;
        }
        int pos = g_rowptr[d] + atomicAdd(&g_fill[d], 1);
        g_csr[pos] = make_int2(s, __float_as_int(w));
    }
}

// ---------------- SGEMM: g_t[n,128] = A[n,K] @ B[K,128] ----------------
// SRC 0: A = x (K=256), plain load.  SRC 1: A = BNrelu(g_agg), B = W2.
// SRC 2: A = BNrelu(g_agg), B = g_Wcat.
// Block 0 also zeroes g_stats for the following gather.
template <int SRC>
__global__ void __launch_bounds__(256) k_sgemm(const float* __restrict__ Aext,
                                               const float* __restrict__ Bext) {
    const int K = (SRC == 0) ? 256 : 128;
    const float* A = (SRC == 0) ? Aext : g_agg;
    const float* B = (SRC == 2) ? g_Wcat : Bext;

    __shared__ float As[16][132];  // transposed: As[k][row]
    __shared__ float Bs[16][128];
    int row0 = blockIdx.x * 128;
    int tid = threadIdx.x;
    int tx = tid & 15;
    int ty = tid >> 4;

    if (blockIdx.x == 0) g_stats[tid] = 0.0f;  // 256 slots, 256 threads

    float acc[8][8];
#pragma unroll
    for (int i = 0; i < 8; i++)
#pragma unroll
        for (int j = 0; j < 8; j++) acc[i][j] = 0.0f;

    for (int k0 = 0; k0 < K; k0 += 16) {
#pragma unroll
        for (int l = 0; l < 2; l++) {
            int f  = tid + l * 256;
            int r  = f >> 2;
            int c4 = f & 3;
            int gr = row0 + r;
            float4 v = make_float4(0.f, 0.f, 0.f, 0.f);
            if (gr < NN) {
                v = *(const float4*)(A + (size_t)gr * K + k0 + c4 * 4);
                if (SRC != 0) {
                    int c = k0 + c4 * 4;
                    v.x = fmaxf(fmaf(v.x, g_scale[c + 0], g_shift[c + 0]), 0.f);
                    v.y = fmaxf(fmaf(v.y, g_scale[c + 1], g_shift[c + 1]), 0.f);
                    v.z = fmaxf(fmaf(v.z, g_scale[c + 2], g_shift[c + 2]), 0.f);
                    v.w = fmaxf(fmaf(v.w, g_scale[c + 3], g_shift[c + 3]), 0.f);
                }
            }
            As[c4 * 4 + 0][r] = v.x;
            As[c4 * 4 + 1][r] = v.y;
            As[c4 * 4 + 2][r] = v.z;
            As[c4 * 4 + 3][r] = v.w;
        }
#pragma unroll
        for (int l = 0; l < 2; l++) {
            int f  = tid + l * 256;
            int kr = f >> 5;
            int c4 = f & 31;
            *(float4*)&Bs[kr][c4 * 4] =
                *(const float4*)(B + (size_t)(k0 + kr) * 128 + c4 * 4);
        }
        __syncthreads();
#pragma unroll
        for (int k = 0; k < 16; k++) {
            float4 a0 = *(float4*)&As[k][ty * 8];
            float4 a1 = *(float4*)&As[k][ty * 8 + 4];
            float4 b0 = *(float4*)&Bs[k][tx * 8];
            float4 b1 = *(float4*)&Bs[k][tx * 8 + 4];
            float a[8] = {a0.x, a0.y, a0.z, a0.w, a1.x, a1.y, a1.z, a1.w};
            float b[8] = {b0.x, b0.y, b0.z, b0.w, b1.x, b1.y, b1.z, b1.w};
#pragma unroll
            for (int i = 0; i < 8; i++)
#pragma unroll
                for (int j = 0; j < 8; j++) acc[i][j] += a[i] * b[j];
        }
        __syncthreads();
    }
#pragma unroll
    for (int i = 0; i < 8; i++) {
        int gr = row0 + ty * 8 + i;
        if (gr < NN) {
            *(float4*)(g_t + (size_t)gr * 128 + tx * 8) =
                make_float4(acc[i][0], acc[i][1], acc[i][2], acc[i][3]);
            *(float4*)(g_t + (size_t)gr * 128 + tx * 8 + 4) =
                make_float4(acc[i][4], acc[i][5], acc[i][6], acc[i][7]);
        }
    }
}

// ---------------- CSR gather: one warp per dst node ----------------
// EPI 0: agg = sum + bias -> g_agg; accumulate BN stats into g_stats.
// EPI 1: write mu/logstd (+bias) directly to out.
template <int EPI>
__global__ void __launch_bounds__(256) k_gather(const float* __restrict__ b0,
                                                const float* __restrict__ b1v,
                                                float* __restrict__ out) {
    __shared__ float s_part[8][256];
    int tid  = threadIdx.x;
    int lane = tid & 31;
    int wid  = tid >> 5;
    int warp = (blockIdx.x * 256 + tid) >> 5;
    int nw   = (gridDim.x * 256) >> 5;
    int c    = lane * 4;

    float rs0 = 0.f, rs1 = 0.f, rs2 = 0.f, rs3 = 0.f;   // stats sum
    float rq0 = 0.f, rq1 = 0.f, rq2 = 0.f, rq3 = 0.f;   // stats sumsq

    for (int d = warp; d < NN; d += nw) {
        int beg = g_rowptr[d];
        int end = g_rowptr[d + 1];
        float ax = 0.f, ay = 0.f, az = 0.f, aw = 0.f;
        for (int j = beg; j < end; j++) {
            int2  e = g_csr[j];                 // broadcast across warp
            float w = __int_as_float(e.y);
            float4 v = *(const float4*)(g_t + (size_t)e.x * 128 + c);
            ax = fmaf(v.x, w, ax);
            ay = fmaf(v.y, w, ay);
            az = fmaf(v.z, w, az);
            aw = fmaf(v.w, w, aw);
        }
        if (EPI == 0) {
            ax += b0[c + 0]; ay += b0[c + 1]; az += b0[c + 2]; aw += b0[c + 3];
            *(float4*)(g_agg + (size_t)d * 128 + c) = make_float4(ax, ay, az, aw);
            rs0 += ax; rs1 += ay; rs2 += az; rs3 += aw;
            rq0 = fmaf(ax, ax, rq0); rq1 = fmaf(ay, ay, rq1);
            rq2 = fmaf(az, az, rq2); rq3 = fmaf(aw, aw, rq3);
        } else {
            const float* bb = (lane < 16) ? b0 : b1v;      // bmu | bls
            int cc = (lane < 16) ? c : c - 64;
            ax += bb[cc + 0]; ay += bb[cc + 1]; az += bb[cc + 2]; aw += bb[cc + 3];
            float* dst = (lane < 16)
                ? out + (size_t)d * 64 + cc
                : out + (size_t)NN * 64 + (size_t)d * 64 + cc;
            *(float4*)dst = make_float4(ax, ay, az, aw);
        }
    }

    if (EPI == 0) {
        s_part[wid][c + 0] = rs0; s_part[wid][c + 1] = rs1;
        s_part[wid][c + 2] = rs2; s_part[wid][c + 3] = rs3;
        s_part[wid][128 + c + 0] = rq0; s_part[wid][128 + c + 1] = rq1;
        s_part[wid][128 + c + 2] = rq2; s_part[wid][128 + c + 3] = rq3;
        __syncthreads();
        float v = 0.f;
#pragma unroll
        for (int w = 0; w < 8; w++) v += s_part[w][tid];
        atomicAdd(&g_stats[tid], v);
    }
}

// ---------------- BN params from stats ----------------
__global__ void k_bnparams(const float* __restrict__ g, const float* __restrict__ bt) {
    int c = threadIdx.x;  // 128
    float m   = g_stats[c] * (1.0f / NN);
    float var = g_stats[128 + c] * (1.0f / NN) - m * m;
    float sc  = rsqrtf(var + EPSV) * g[c];
    g_scale[c] = sc;
    g_shift[c] = bt[c] - m * sc;
}

// ---------------- pack [Wmu | Wls] ----------------
__global__ void k_pack_w(const float* __restrict__ Wmu, const float* __restrict__ Wls) {
    int i = blockIdx.x * blockDim.x + threadIdx.x;
    if (i < 128 * 128) {
        int k = i >> 7, j = i & 127;
        g_Wcat[i] = (j < 64) ? Wmu[k * 64 + j] : Wls[k * 64 + (j - 64)];
    }
}

// ---------------- launch: kernel launches ONLY ----------------
extern "C" void kernel_launch(void* const* d_in, const int* in_sizes, int n_in,
                              void* d_out, int out_size) {
    const float* x   = (const float*)d_in[0];
    const float* W1  = (const float*)d_in[1];
    const float* b1  = (const float*)d_in[2];
    const float* g1  = (const float*)d_in[3];
    const float* bt1 = (const float*)d_in[4];
    const float* W2  = (const float*)d_in[5];
    const float* b2  = (const float*)d_in[6];
    const float* g2  = (const float*)d_in[7];
    const float* bt2 = (const float*)d_in[8];
    const float* Wmu = (const float*)d_in[9];
    const float* bmu = (const float*)d_in[10];
    const float* Wls = (const float*)d_in[11];
    const float* bls = (const float*)d_in[12];
    const int*   ei  = (const int*)d_in[13];
    const int* src = ei;
    const int* dst = ei + EE;
    float* out = (float*)d_out;

    const int GEMM_GRID = (NN + 127) / 128;

    // --- CSR build ---
    k_init<<<(NN + 255) / 256, 256>>>();
    k_count<<<(EE + 255) / 256, 256>>>(dst);
    k_dinv<<<(NN + 255) / 256, 256>>>();
    k_scan1<<<NB, 1024>>>();
    k_scan2<<<1, 1>>>();
    k_scan3<<<NB, 1024>>>();
    k_fill<<<4096, 256>>>(src, dst);

    // --- layer 1 ---
    k_sgemm<0><<<GEMM_GRID, 256>>>(x, W1);
    k_gather<0><<<2048, 256>>>(b1, nullptr, nullptr);
    k_bnparams<<<1, 128>>>(g1, bt1);

    // --- layer 2 ---
    k_sgemm<1><<<GEMM_GRID, 256>>>(nullptr, W2);
    k_gather<0><<<2048, 256>>>(b2, nullptr, nullptr);
    k_bnparams<<<1, 128>>>(g2, bt2);

    // --- layer 3 (fused mu/logstd) ---
    k_pack_w<<<64, 256>>>(Wmu, Wls);
    k_sgemm<2><<<GEMM_GRID, 256>>>(nullptr, nullptr);
    k_gather<1><<<2048, 256>>>(bmu, bls, out);
}